// round 5
// baseline (speedup 1.0000x reference)
#include <cuda_runtime.h>

#define NMAX   100000
#define NNZMAX 3200000
#define BV     32

// Scratch (static __device__ — no allocations allowed).
__device__ float g_xT[(size_t)NMAX * BV];          // x transposed (N, B)
__device__ int   g_count [NMAX];
__device__ int   g_offset[NMAX];                   // exclusive prefix of counts
__device__ int   g_cursor[NMAX];                   // running fill ptr -> becomes end ptr
__device__ int   g_blocksum[1024];
__device__ int2  g_edges[NNZMAX];                  // dst-sorted (src, val_bits)

// ---------------------------------------------------------------------------
__global__ void zero_count_kernel(int M) {
    int i = blockIdx.x * blockDim.x + threadIdx.x;
    if (i < M) g_count[i] = 0;
}

// Transpose x (B, N) -> g_xT (N, B).
__global__ void transpose_x_kernel(const float* __restrict__ x, int N, int B) {
    __shared__ float tile[32][33];
    int n0 = blockIdx.x * 32;
    int tx = threadIdx.x, ty = threadIdx.y;
    int n = n0 + tx;
    if (ty < B && n < N) tile[ty][tx] = x[(size_t)ty * N + n];
    __syncthreads();
    int nw = n0 + ty;
    if (tx < B && nw < N) g_xT[(size_t)nw * BV + tx] = tile[tx][ty];
}

// Histogram of dst.
__global__ void hist_kernel(const int* __restrict__ idx, int nnz) {
    int i = blockIdx.x * blockDim.x + threadIdx.x;
    if (i < nnz) atomicAdd(&g_count[idx[nnz + i]], 1);
}

// Exclusive scan, level 1: 1024-element blocks.
__global__ void scan_block_kernel(int M) {
    __shared__ int sh[1024];
    int gid = blockIdx.x * 1024 + threadIdx.x;
    int v = (gid < M) ? g_count[gid] : 0;
    sh[threadIdx.x] = v;
    __syncthreads();
    for (int off = 1; off < 1024; off <<= 1) {
        int t = (threadIdx.x >= off) ? sh[threadIdx.x - off] : 0;
        __syncthreads();
        sh[threadIdx.x] += t;
        __syncthreads();
    }
    if (gid < M) g_offset[gid] = sh[threadIdx.x] - v;     // exclusive
    if (threadIdx.x == 1023) g_blocksum[blockIdx.x] = sh[1023];
}

// Exclusive scan, level 2: scan the block sums (nblk <= 1024) in one block.
__global__ void scan_top_kernel(int nblk) {
    __shared__ int sh[1024];
    int v = (threadIdx.x < nblk) ? g_blocksum[threadIdx.x] : 0;
    sh[threadIdx.x] = v;
    __syncthreads();
    for (int off = 1; off < 1024; off <<= 1) {
        int t = (threadIdx.x >= off) ? sh[threadIdx.x - off] : 0;
        __syncthreads();
        sh[threadIdx.x] += t;
        __syncthreads();
    }
    if (threadIdx.x < nblk) g_blocksum[threadIdx.x] = sh[threadIdx.x] - v;
}

// Add block offsets; initialize cursors.
__global__ void scan_add_kernel(int M) {
    int gid = blockIdx.x * 1024 + threadIdx.x;
    if (gid < M) {
        int o = g_offset[gid] + g_blocksum[blockIdx.x];
        g_offset[gid] = o;
        g_cursor[gid] = o;
    }
}

// Scatter edges into dst-sorted order (packed 8B records).
__global__ void scatter_kernel(const int* __restrict__ idx,
                               const float* __restrict__ vals, int nnz) {
    int i = blockIdx.x * blockDim.x + threadIdx.x;
    if (i >= nnz) return;
    int src = idx[i];
    int dst = idx[nnz + i];
    int pos = atomicAdd(&g_cursor[dst], 1);
    g_edges[pos] = make_int2(src, __float_as_int(vals[i]));
}

// Gather: one warp per dst row (lane = batch). Fused transpose + bias + out.
__global__ void gather_out_kernel(float* __restrict__ out,
                                  const float* __restrict__ bias, int M, int B) {
    __shared__ float tile[32][33];
    int m0 = blockIdx.x * 32;
    int tx = threadIdx.x, ty = threadIdx.y;      // warp ty handles row m0+ty
    int m = m0 + ty;

    float sum = 0.f;
    if (m < M) {
        int p = g_offset[m];
        int e = g_cursor[m];                      // == offset + count after scatter
        // Unroll by 2 for a bit of MLP on the dependent edge->xT chain.
        for (; p + 1 < e; p += 2) {
            int2 e0 = g_edges[p];
            int2 e1 = g_edges[p + 1];
            float x0 = g_xT[(size_t)e0.x * BV + tx];
            float x1 = g_xT[(size_t)e1.x * BV + tx];
            sum += __int_as_float(e0.y) * x0;
            sum += __int_as_float(e1.y) * x1;
        }
        if (p < e) {
            int2 e0 = g_edges[p];
            sum += __int_as_float(e0.y) * g_xT[(size_t)e0.x * BV + tx];
        }
    }
    tile[ty][tx] = sum;
    __syncthreads();
    int mo = m0 + tx;
    if (mo < M && ty < B)
        out[(size_t)ty * M + mo] = tile[tx][ty] + __ldg(bias + mo);
}

// ---------------------------------------------------------------------------
extern "C" void kernel_launch(void* const* d_in, const int* in_sizes, int n_in,
                              void* d_out, int out_size) {
    const float* x    = (const float*)d_in[0];   // (B, N, 1)
    const int*   idx  = (const int*)  d_in[1];   // (2, NNZ)
    const float* vals = (const float*)d_in[2];   // (NNZ,)
    const float* bias = (const float*)d_in[3];   // (M, 1)
    float*       out  = (float*)d_out;           // (B, M, 1)

    int M   = in_sizes[3];
    int NNZ = in_sizes[1] / 2;
    int B   = out_size / M;
    int N   = in_sizes[0] / B;
    int nblk = (M + 1023) / 1024;

    zero_count_kernel<<<(M + 255) / 256, 256>>>(M);

    {
        dim3 blk(32, 32);
        transpose_x_kernel<<<(N + 31) / 32, blk>>>(x, N, B);
    }

    hist_kernel<<<(NNZ + 255) / 256, 256>>>(idx, NNZ);

    scan_block_kernel<<<nblk, 1024>>>(M);
    scan_top_kernel<<<1, 1024>>>(nblk);
    scan_add_kernel<<<nblk, 1024>>>(M);

    scatter_kernel<<<(NNZ + 255) / 256, 256>>>(idx, vals, NNZ);

    {
        dim3 blk(32, 32);
        gather_out_kernel<<<(M + 31) / 32, blk>>>(out, bias, M, B);
    }
}